// round 16
// baseline (speedup 1.0000x reference)
#include <cuda_runtime.h>
#include <cuda_fp16.h>
#include <cstdint>
#include <cstddef>

#define B_ 32
#define T_ 2048
#define W_ 1024
#define G_ 16
#define D_ 64
#define INV_TM1 (1.0f/2047.0f)

// ---------------- scratch (static device memory; no allocations) ----------------
__device__ __half g_covh[(size_t)B_ * W_ * W_];         // f16 Gram (raw accumulators), upper tiles
__device__ __half g_xh[(size_t)B_ * T_ * W_];           // fp16(x), uncentered, [b][t][w]
__device__ float  g_psum[2048 * W_];                    // per-(32-row chunk) column partial sums
__device__ float  g_mu[B_ * W_];                        // mean of fp16 values over T
__device__ float  g_f[B_ * W_];                         // 1/sqrt((diag - T*mu^2)*INV_TM1)
__device__ float  g_partial[B_ * G_];

// ---------------- 1) FUSED: x -> fp16 store + column psums + fp32 MLP ----------------
__global__ __launch_bounds__(256, 4) void fused_kernel(const float* __restrict__ x,
                                                       const float* __restrict__ W1,
                                                       const float* __restrict__ b1,
                                                       const float* __restrict__ W2,
                                                       const float* __restrict__ b2,
                                                       float* __restrict__ out) {
    __shared__ __align__(16) float tile[32 * 65 * 4];   // [32 rows][65 float4] padded
    __shared__ __align__(16) float W1s[4096];           // 4 groups x 16 x 64
    __shared__ float psum[4][256];
    __shared__ float opart[256];
    __shared__ float b1s[64], W2s[64], b2s[4];

    int tid  = threadIdx.x;
    int quad = blockIdx.y;
    int bchunk = blockIdx.x;                            // 0..2047
    size_t row0 = (size_t)bchunk * 32;                  // global row (b*T + t)

#pragma unroll
    for (int i = 0; i < 4; ++i)
        ((float4*)W1s)[tid + i * 256] = ((const float4*)(W1 + (size_t)quad * 4096))[tid + i * 256];
    if (tid < 64) { b1s[tid] = b1[quad * 64 + tid]; W2s[tid] = W2[quad * 64 + tid]; }
    if (tid < 4)  b2s[tid]  = b2[quad * 4 + tid];

    // ---- phase 1: stream 32x256 fp32, convert+store fp16, psum of rounded vals ----
    int c4 = tid & 63, rgrp = tid >> 6;
    const float* xp = x + row0 * W_ + quad * 256;
    __half* hp = g_xh + row0 * W_ + quad * 256;
    float4 lsum = make_float4(0.f, 0.f, 0.f, 0.f);
#pragma unroll
    for (int k = 0; k < 8; ++k) {
        int r = k * 4 + rgrp;
        float4 v = __ldg((const float4*)(xp + (size_t)r * W_) + c4);
        __half2 h01 = __floats2half2_rn(v.x, v.y);
        __half2 h23 = __floats2half2_rn(v.z, v.w);
        uint2 u; u.x = *(uint32_t*)&h01; u.y = *(uint32_t*)&h23;
        *((uint2*)(hp + (size_t)r * W_) + c4) = u;
        float2 f01 = __half22float2(h01);
        float2 f23 = __half22float2(h23);
        lsum.x += f01.x; lsum.y += f01.y; lsum.z += f23.x; lsum.w += f23.y;
        ((float4*)tile)[r * 65 + c4] = v;               // raw fp32 for exact MLP
    }
    ((float4*)psum)[rgrp * 64 + c4] = lsum;
    __syncthreads();

    if (tid < 64) {                                      // deterministic 4-way reduce
        float4 a = ((float4*)psum)[tid];
        float4 bb = ((float4*)psum)[64 + tid];
        float4 c = ((float4*)psum)[128 + tid];
        float4 d = ((float4*)psum)[192 + tid];
        float4 s = make_float4(a.x + bb.x + c.x + d.x, a.y + bb.y + c.y + d.y,
                               a.z + bb.z + c.z + d.z, a.w + bb.w + c.w + d.w);
        ((float4*)(g_psum + (size_t)bchunk * W_ + quad * 256))[tid] = s;
    }

    // ---- phase 2: fp32 MLP, thread = (group, h-half, row) ----
    int g  = tid >> 6;
    int hh = (tid >> 5) & 1;
    int row = tid & 31;
    float h[8];
#pragma unroll
    for (int j = 0; j < 8; ++j) h[j] = b1s[g * 16 + hh * 8 + j];
    const float4* xr = (const float4*)tile + row * 65 + g * 16;
#pragma unroll
    for (int j4 = 0; j4 < 16; ++j4) {
        float4 xv = xr[j4];
#pragma unroll
        for (int j = 0; j < 8; ++j) {
            float4 wv = ((const float4*)W1s)[(g * 16 + hh * 8 + j) * 16 + j4];
            h[j] = fmaf(wv.x, xv.x, h[j]); h[j] = fmaf(wv.y, xv.y, h[j]);
            h[j] = fmaf(wv.z, xv.z, h[j]); h[j] = fmaf(wv.w, xv.w, h[j]);
        }
    }
    float o = 0.f;
#pragma unroll
    for (int j = 0; j < 8; ++j) o += W2s[g * 16 + hh * 8 + j] * fmaxf(h[j], 0.f);
    opart[tid] = o;
    __syncthreads();
    if (hh == 0)
        out[(row0 + row) * G_ + quad * 4 + g] = o + opart[tid + 32] + b2s[g];
}

// ---------------- 2) fp16 mma.sync Gram, 64x64 warp tile, 4 warps/CTA ----------------
#define KS  32
#define NST 3

__device__ __forceinline__ void cp16(uint32_t saddr, const void* gptr) {
    asm volatile("cp.async.cg.shared.global [%0], [%1], 16;\n" :: "r"(saddr), "l"(gptr));
}

__global__ __launch_bounds__(128, 4) void cov_mma_kernel() {
    int b = blockIdx.y;
    int rem = blockIdx.x, bi = 0, n = 8;
    while (rem >= n) { rem -= n; --n; ++bi; }
    int bj = bi + rem;
    bool diag = (bi == bj);

    __shared__ __align__(1024) unsigned char smem_raw[NST * 16384];
    uint32_t sbase = (uint32_t)__cvta_generic_to_shared(smem_raw);

    const __half* XU = g_xh + (size_t)b * T_ * W_ + bi * 128;
    const __half* XV = g_xh + (size_t)b * T_ * W_ + bj * 128;

    int tid = threadIdx.x;

    for (int s = 0; s < NST - 1; ++s) {
        uint32_t sU = sbase + s * 16384, sV = sU + 8192;
#pragma unroll
        for (int i = 0; i < 4; ++i) {
            int c = tid + i * 128;
            int t = c >> 4, cb = c & 15;
            uint32_t o = (uint32_t)(t * 256 + ((cb ^ (t & 7)) << 4));
            cp16(sU + o, XU + (size_t)(s * KS + t) * W_ + cb * 8);
            if (!diag) cp16(sV + o, XV + (size_t)(s * KS + t) * W_ + cb * 8);
        }
        asm volatile("cp.async.commit_group;\n");
    }

    uint32_t acc[4][8][2];
#pragma unroll
    for (int a = 0; a < 4; ++a)
#pragma unroll
        for (int c = 0; c < 8; ++c) { acc[a][c][0] = 0u; acc[a][c][1] = 0u; }

    int lane = tid & 31, wid = tid >> 5;
    int wm = wid & 1, wn = wid >> 1;
    int arow = (lane & 7) + ((lane >> 4) << 3);
    int acbo = (lane >> 3) & 1;
    int brow = (lane & 7) + (((lane >> 3) & 1) << 3);
    int bcbo = lane >> 4;

    const int NKB = T_ / KS;
    for (int kb = 0; kb < NKB; ++kb) {
        asm volatile("cp.async.wait_group 1;\n");
        __syncthreads();

        int nk = kb + NST - 1;
        if (nk < NKB) {
            int s = nk % NST;
            uint32_t sU = sbase + s * 16384, sV = sU + 8192;
#pragma unroll
            for (int i = 0; i < 4; ++i) {
                int c = tid + i * 128;
                int t = c >> 4, cb = c & 15;
                uint32_t o = (uint32_t)(t * 256 + ((cb ^ (t & 7)) << 4));
                cp16(sU + o, XU + (size_t)(nk * KS + t) * W_ + cb * 8);
                if (!diag) cp16(sV + o, XV + (size_t)(nk * KS + t) * W_ + cb * 8);
            }
            asm volatile("cp.async.commit_group;\n");
        }

        int st = kb % NST;
        uint32_t sU = sbase + st * 16384;
        uint32_t sVd = diag ? sU : (sU + 8192);
#pragma unroll
        for (int ks = 0; ks < KS / 16; ++ks) {
            int t0 = ks * 16;
            uint32_t a[4][4];
#pragma unroll
            for (int mi = 0; mi < 4; ++mi) {
                int cbA = ((wm * 64 + mi * 16) >> 3) + acbo;
                int row = t0 + arow;
                uint32_t addr = sU + row * 256 + ((cbA ^ (row & 7)) << 4);
                asm volatile("ldmatrix.sync.aligned.m8n8.x4.trans.shared.b16 {%0,%1,%2,%3}, [%4];\n"
                    : "=r"(a[mi][0]), "=r"(a[mi][1]), "=r"(a[mi][2]), "=r"(a[mi][3]) : "r"(addr));
            }
            uint32_t bfr[8][2];
#pragma unroll
            for (int nb = 0; nb < 4; ++nb) {
                int cbB = ((wn * 64 + nb * 16) >> 3) + bcbo;
                int row = t0 + brow;
                uint32_t addr = sVd + row * 256 + ((cbB ^ (row & 7)) << 4);
                uint32_t r0, r1, r2, r3;
                asm volatile("ldmatrix.sync.aligned.m8n8.x4.trans.shared.b16 {%0,%1,%2,%3}, [%4];\n"
                    : "=r"(r0), "=r"(r1), "=r"(r2), "=r"(r3) : "r"(addr));
                bfr[nb * 2][0] = r0; bfr[nb * 2][1] = r1;
                bfr[nb * 2 + 1][0] = r2; bfr[nb * 2 + 1][1] = r3;
            }
#pragma unroll
            for (int mi = 0; mi < 4; ++mi)
#pragma unroll
                for (int ni = 0; ni < 8; ++ni)
                    asm volatile("mma.sync.aligned.m16n8k16.row.col.f16.f16.f16.f16 "
                        "{%0,%1},{%2,%3,%4,%5},{%6,%7},{%0,%1};\n"
                        : "+r"(acc[mi][ni][0]), "+r"(acc[mi][ni][1])
                        : "r"(a[mi][0]), "r"(a[mi][1]), "r"(a[mi][2]), "r"(a[mi][3]),
                          "r"(bfr[ni][0]), "r"(bfr[ni][1]));
        }
    }

    __half* Cb = g_covh + (size_t)b * W_ * W_;
    int g = lane >> 2, tg = lane & 3;
#pragma unroll
    for (int mi = 0; mi < 4; ++mi) {
        int m = bi * 128 + wm * 64 + mi * 16 + g;
#pragma unroll
        for (int ni = 0; ni < 8; ++ni) {
            int n2 = bj * 128 + wn * 64 + ni * 8 + tg * 2;
            *(uint32_t*)(Cb + (size_t)m * W_ + n2)       = acc[mi][ni][0];
            *(uint32_t*)(Cb + (size_t)(m + 8) * W_ + n2) = acc[mi][ni][1];
        }
    }
}

// ---------------- 3) merged: mu from psum + f from cov diagonal ----------------
__global__ __launch_bounds__(256) void muf_kernel() {
    int i = blockIdx.x * 256 + threadIdx.x;    // 32768 (b,w)
    int b = i >> 10, w = i & 1023;
    float s = 0.f;
#pragma unroll 8
    for (int c = 0; c < 64; ++c) s += g_psum[(size_t)(b * 64 + c) * W_ + w];
    float mu = s * (1.0f / T_);
    g_mu[i] = mu;
    float diag = __half2float(g_covh[(size_t)b * W_ * W_ + (size_t)w * W_ + w]);
    float var = (diag - (float)T_ * mu * mu) * INV_TM1;
    g_f[i] = (var > 0.f) ? rsqrtf(var) : 0.f;
}

// ---------------- 4) EMA scan: FORCED prefetch of all 32 batch loads (MLP=32) ----------------
__global__ __launch_bounds__(256) void ema_kernel(const float* __restrict__ ema_in,
                                                  float* __restrict__ ema_out) {
    int v2 = blockIdx.x * 256 + threadIdx.x;    // 0..511
    int w = blockIdx.y;
    int v = v2 * 2;
    if (v + 1 < w) return;
    const __half2* cp = (const __half2*)(g_covh + (size_t)w * W_ + v);

    uint32_t craw[B_];                           // 32 independent loads, compiler CANNOT sink
#pragma unroll
    for (int b = 0; b < B_; ++b)
        asm volatile("ld.global.nc.b32 %0, [%1];"
                     : "=r"(craw[b]) : "l"(cp + (size_t)b * (W_ * W_ / 2)));

    float2 e = *(const float2*)(ema_in + (size_t)w * W_ + v);
#pragma unroll
    for (int b = 0; b < B_; ++b) {
        float2 c2 = __half22float2(*(__half2*)&craw[b]);
        float mw = g_mu[b * W_ + w];
        float fw = g_f[b * W_ + w];
        float2 mv = *(const float2*)(g_mu + b * W_ + v);
        float2 fv = *(const float2*)(g_f + b * W_ + v);
        float c0 = (c2.x - (float)T_ * mw * mv.x) * INV_TM1;
        float c1 = (c2.y - (float)T_ * mw * mv.y) * INV_TM1;
        float corr0 = fminf(1.f, fmaxf(-1.f, c0 * fw * fv.x));
        float corr1 = fminf(1.f, fmaxf(-1.f, c1 * fw * fv.y));
        if (fabsf(corr0) > 0.5f) e.x = 0.9f * e.x + 0.1f * corr0;
        if (fabsf(corr1) > 0.5f) e.y = 0.9f * e.y + 0.1f * corr1;
    }
    if (v >= w) *(float2*)(ema_out + (size_t)w * W_ + v) = e;
    else        ema_out[(size_t)w * W_ + v + 1] = e.y;     // v == w-1 boundary
}

// ---------------- 4b) mirror: fill lower triangle via tiled smem transpose ----------------
__global__ __launch_bounds__(256) void mirror_kernel(float* __restrict__ ema_out) {
    int bid = blockIdx.x;                       // 0..527 upper (ti<=tj) 32x32 tiles
    int ti = 0, rem = bid, n = 32;
    while (rem >= n) { rem -= n; --n; ++ti; }
    int tj = ti + rem;

    __shared__ float tile[32][33];
    int tx = threadIdx.x & 31, ty = threadIdx.x >> 5;   // ty 0..7
#pragma unroll
    for (int k = 0; k < 4; ++k) {
        int r = k * 8 + ty;
        tile[r][tx] = ema_out[(size_t)(ti * 32 + r) * W_ + tj * 32 + tx];
    }
    __syncthreads();
    if (ti == tj) {
#pragma unroll
        for (int k = 0; k < 4; ++k) {
            int r = k * 8 + ty;
            if (tx < r) ema_out[(size_t)(ti * 32 + r) * W_ + ti * 32 + tx] = tile[tx][r];
        }
    } else {
#pragma unroll
        for (int k = 0; k < 4; ++k) {
            int r = k * 8 + ty;
            ema_out[(size_t)(tj * 32 + r) * W_ + ti * 32 + tx] = tile[tx][r];
        }
    }
}

// ---------------- 5) per-(g,b) off-diagonal |corr| partial sums, half2 loads ----------------
__global__ __launch_bounds__(256) void corr_partial_kernel() {
    int g = blockIdx.x, b = blockIdx.y;
    const __half* covb = g_covh + (size_t)b * (W_ * W_);
    const float* fs   = g_f + b * W_;
    const float* mn   = g_mu + b * W_;
    int tid = threadIdx.x;
    float s = 0.f;
    for (int i = tid; i < D_ * D_ / 2; i += 256) {      // 2048 half2 elements
        int d = i >> 5, j = i & 31;                      // row d, half2-col j
        int w = g * 64 + d, v = g * 64 + j * 2;
        float2 c2 = __half22float2(*(const __half2*)(covb + (size_t)w * W_ + v));
        float c0 = (c2.x - (float)T_ * mn[w] * mn[v])     * INV_TM1;
        float c1 = (c2.y - (float)T_ * mn[w] * mn[v + 1]) * INV_TM1;
        float corr0 = fminf(1.f, fmaxf(-1.f, c0 * fs[w] * fs[v]));
        float corr1 = fminf(1.f, fmaxf(-1.f, c1 * fs[w] * fs[v + 1]));
        if (d != j * 2)     s += fabsf(corr0);
        if (d != j * 2 + 1) s += fabsf(corr1);
    }
    __shared__ float red[256];
    red[tid] = s;
    __syncthreads();
    for (int off = 128; off > 0; off >>= 1) {
        if (tid < off) red[tid] += red[tid + off];
        __syncthreads();
    }
    if (tid == 0) g_partial[b * G_ + g] = red[0];
}

__global__ void corr_final_kernel(float* __restrict__ out_corr) {
    int g = threadIdx.x;
    if (g < G_) {
        float s = 0.f;
        for (int b = 0; b < B_; ++b) s += g_partial[b * G_ + g];  // fixed order: deterministic
        out_corr[g] = s * (1.0f / ((float)(D_ * D_ - D_) * (float)B_));
    }
}

// ---------------- launch ----------------
extern "C" void kernel_launch(void* const* d_in, const int* in_sizes, int n_in,
                              void* d_out, int out_size) {
    (void)in_sizes; (void)n_in; (void)out_size;
    const float* x   = (const float*)d_in[0];
    const float* ema = (const float*)d_in[1];
    const float* W1  = (const float*)d_in[2];
    const float* b1  = (const float*)d_in[3];
    const float* W2  = (const float*)d_in[4];
    const float* b2  = (const float*)d_in[5];

    float* out      = (float*)d_out;                      // (B,T,G) = 1048576
    float* out_corr = out + (size_t)B_ * T_ * G_;         // (G,)    = 16
    float* out_ema  = out_corr + G_;                      // (W,W)   = 1048576

    fused_kernel<<<dim3(B_ * T_ / 32, 4), 256>>>(x, W1, b1, W2, b2, out);   // idx 0
    cov_mma_kernel<<<dim3(36, B_), 128>>>();                                // idx 1
    muf_kernel<<<(B_ * W_) / 256, 256>>>();                                 // idx 2
    ema_kernel<<<dim3(2, W_), 256>>>(ema, out_ema);                         // idx 3
    mirror_kernel<<<528, 256>>>(out_ema);                                   // idx 4
    corr_partial_kernel<<<dim3(G_, B_), 256>>>();                           // idx 5
    corr_final_kernel<<<1, 32>>>(out_corr);                                 // idx 6
}

// round 17
// speedup vs baseline: 1.0059x; 1.0059x over previous
#include <cuda_runtime.h>
#include <cuda_fp16.h>
#include <cstdint>
#include <cstddef>

#define B_ 32
#define T_ 2048
#define W_ 1024
#define G_ 16
#define D_ 64
#define INV_TM1 (1.0f/2047.0f)

// ---------------- scratch (static device memory; no allocations) ----------------
__device__ __half g_covh[(size_t)B_ * W_ * W_];         // f16 Gram (raw accumulators), upper tiles
__device__ __half g_xh[(size_t)B_ * T_ * W_];           // fp16(x), uncentered, [b][t][w]
__device__ float  g_psum[2048 * W_];                    // per-(32-row chunk) column partial sums
__device__ float  g_mt[B_ * W_];                        // m~ = mu * f * sqrt(T*INV_TM1)
__device__ float  g_ft[B_ * W_];                        // f~ = f * sqrt(INV_TM1)
__device__ float  g_partial[B_ * G_];

// ---------------- 1) FUSED: x -> fp16 store + column psums + fp32 MLP ----------------
__global__ __launch_bounds__(256, 4) void fused_kernel(const float* __restrict__ x,
                                                       const float* __restrict__ W1,
                                                       const float* __restrict__ b1,
                                                       const float* __restrict__ W2,
                                                       const float* __restrict__ b2,
                                                       float* __restrict__ out) {
    __shared__ __align__(16) float tile[32 * 65 * 4];   // [32 rows][65 float4] padded
    __shared__ __align__(16) float W1s[4096];           // 4 groups x 16 x 64
    __shared__ float psum[4][256];
    __shared__ float opart[256];
    __shared__ float b1s[64], W2s[64], b2s[4];

    int tid  = threadIdx.x;
    int quad = blockIdx.y;
    int bchunk = blockIdx.x;                            // 0..2047
    size_t row0 = (size_t)bchunk * 32;                  // global row (b*T + t)

#pragma unroll
    for (int i = 0; i < 4; ++i)
        ((float4*)W1s)[tid + i * 256] = ((const float4*)(W1 + (size_t)quad * 4096))[tid + i * 256];
    if (tid < 64) { b1s[tid] = b1[quad * 64 + tid]; W2s[tid] = W2[quad * 64 + tid]; }
    if (tid < 4)  b2s[tid]  = b2[quad * 4 + tid];

    // ---- phase 1: stream 32x256 fp32, convert+store fp16, psum of rounded vals ----
    int c4 = tid & 63, rgrp = tid >> 6;
    const float* xp = x + row0 * W_ + quad * 256;
    __half* hp = g_xh + row0 * W_ + quad * 256;
    float4 lsum = make_float4(0.f, 0.f, 0.f, 0.f);
#pragma unroll
    for (int k = 0; k < 8; ++k) {
        int r = k * 4 + rgrp;
        float4 v = __ldg((const float4*)(xp + (size_t)r * W_) + c4);
        __half2 h01 = __floats2half2_rn(v.x, v.y);
        __half2 h23 = __floats2half2_rn(v.z, v.w);
        uint2 u; u.x = *(uint32_t*)&h01; u.y = *(uint32_t*)&h23;
        *((uint2*)(hp + (size_t)r * W_) + c4) = u;
        float2 f01 = __half22float2(h01);
        float2 f23 = __half22float2(h23);
        lsum.x += f01.x; lsum.y += f01.y; lsum.z += f23.x; lsum.w += f23.y;
        ((float4*)tile)[r * 65 + c4] = v;               // raw fp32 for exact MLP
    }
    ((float4*)psum)[rgrp * 64 + c4] = lsum;
    __syncthreads();

    if (tid < 64) {                                      // deterministic 4-way reduce
        float4 a = ((float4*)psum)[tid];
        float4 bb = ((float4*)psum)[64 + tid];
        float4 c = ((float4*)psum)[128 + tid];
        float4 d = ((float4*)psum)[192 + tid];
        float4 s = make_float4(a.x + bb.x + c.x + d.x, a.y + bb.y + c.y + d.y,
                               a.z + bb.z + c.z + d.z, a.w + bb.w + c.w + d.w);
        ((float4*)(g_psum + (size_t)bchunk * W_ + quad * 256))[tid] = s;
    }

    // ---- phase 2: fp32 MLP, thread = (group, h-half, row) ----
    int g  = tid >> 6;
    int hh = (tid >> 5) & 1;
    int row = tid & 31;
    float h[8];
#pragma unroll
    for (int j = 0; j < 8; ++j) h[j] = b1s[g * 16 + hh * 8 + j];
    const float4* xr = (const float4*)tile + row * 65 + g * 16;
#pragma unroll
    for (int j4 = 0; j4 < 16; ++j4) {
        float4 xv = xr[j4];
#pragma unroll
        for (int j = 0; j < 8; ++j) {
            float4 wv = ((const float4*)W1s)[(g * 16 + hh * 8 + j) * 16 + j4];
            h[j] = fmaf(wv.x, xv.x, h[j]); h[j] = fmaf(wv.y, xv.y, h[j]);
            h[j] = fmaf(wv.z, xv.z, h[j]); h[j] = fmaf(wv.w, xv.w, h[j]);
        }
    }
    float o = 0.f;
#pragma unroll
    for (int j = 0; j < 8; ++j) o += W2s[g * 16 + hh * 8 + j] * fmaxf(h[j], 0.f);
    opart[tid] = o;
    __syncthreads();
    if (hh == 0)
        out[(row0 + row) * G_ + quad * 4 + g] = o + opart[tid + 32] + b2s[g];
}

// ---------------- 2) fp16 mma.sync Gram, 64x64 warp tile, 4 warps/CTA ----------------
#define KS  32
#define NST 3

__device__ __forceinline__ void cp16(uint32_t saddr, const void* gptr) {
    asm volatile("cp.async.cg.shared.global [%0], [%1], 16;\n" :: "r"(saddr), "l"(gptr));
}

__global__ __launch_bounds__(128, 4) void cov_mma_kernel() {
    int b = blockIdx.y;
    int rem = blockIdx.x, bi = 0, n = 8;
    while (rem >= n) { rem -= n; --n; ++bi; }
    int bj = bi + rem;
    bool diag = (bi == bj);

    __shared__ __align__(1024) unsigned char smem_raw[NST * 16384];
    uint32_t sbase = (uint32_t)__cvta_generic_to_shared(smem_raw);

    const __half* XU = g_xh + (size_t)b * T_ * W_ + bi * 128;
    const __half* XV = g_xh + (size_t)b * T_ * W_ + bj * 128;

    int tid = threadIdx.x;

    for (int s = 0; s < NST - 1; ++s) {
        uint32_t sU = sbase + s * 16384, sV = sU + 8192;
#pragma unroll
        for (int i = 0; i < 4; ++i) {
            int c = tid + i * 128;
            int t = c >> 4, cb = c & 15;
            uint32_t o = (uint32_t)(t * 256 + ((cb ^ (t & 7)) << 4));
            cp16(sU + o, XU + (size_t)(s * KS + t) * W_ + cb * 8);
            if (!diag) cp16(sV + o, XV + (size_t)(s * KS + t) * W_ + cb * 8);
        }
        asm volatile("cp.async.commit_group;\n");
    }

    uint32_t acc[4][8][2];
#pragma unroll
    for (int a = 0; a < 4; ++a)
#pragma unroll
        for (int c = 0; c < 8; ++c) { acc[a][c][0] = 0u; acc[a][c][1] = 0u; }

    int lane = tid & 31, wid = tid >> 5;
    int wm = wid & 1, wn = wid >> 1;
    int arow = (lane & 7) + ((lane >> 4) << 3);
    int acbo = (lane >> 3) & 1;
    int brow = (lane & 7) + (((lane >> 3) & 1) << 3);
    int bcbo = lane >> 4;

    const int NKB = T_ / KS;
    for (int kb = 0; kb < NKB; ++kb) {
        asm volatile("cp.async.wait_group 1;\n");
        __syncthreads();

        int nk = kb + NST - 1;
        if (nk < NKB) {
            int s = nk % NST;
            uint32_t sU = sbase + s * 16384, sV = sU + 8192;
#pragma unroll
            for (int i = 0; i < 4; ++i) {
                int c = tid + i * 128;
                int t = c >> 4, cb = c & 15;
                uint32_t o = (uint32_t)(t * 256 + ((cb ^ (t & 7)) << 4));
                cp16(sU + o, XU + (size_t)(nk * KS + t) * W_ + cb * 8);
                if (!diag) cp16(sV + o, XV + (size_t)(nk * KS + t) * W_ + cb * 8);
            }
            asm volatile("cp.async.commit_group;\n");
        }

        int st = kb % NST;
        uint32_t sU = sbase + st * 16384;
        uint32_t sVd = diag ? sU : (sU + 8192);
#pragma unroll
        for (int ks = 0; ks < KS / 16; ++ks) {
            int t0 = ks * 16;
            uint32_t a[4][4];
#pragma unroll
            for (int mi = 0; mi < 4; ++mi) {
                int cbA = ((wm * 64 + mi * 16) >> 3) + acbo;
                int row = t0 + arow;
                uint32_t addr = sU + row * 256 + ((cbA ^ (row & 7)) << 4);
                asm volatile("ldmatrix.sync.aligned.m8n8.x4.trans.shared.b16 {%0,%1,%2,%3}, [%4];\n"
                    : "=r"(a[mi][0]), "=r"(a[mi][1]), "=r"(a[mi][2]), "=r"(a[mi][3]) : "r"(addr));
            }
            uint32_t bfr[8][2];
#pragma unroll
            for (int nb = 0; nb < 4; ++nb) {
                int cbB = ((wn * 64 + nb * 16) >> 3) + bcbo;
                int row = t0 + brow;
                uint32_t addr = sVd + row * 256 + ((cbB ^ (row & 7)) << 4);
                uint32_t r0, r1, r2, r3;
                asm volatile("ldmatrix.sync.aligned.m8n8.x4.trans.shared.b16 {%0,%1,%2,%3}, [%4];\n"
                    : "=r"(r0), "=r"(r1), "=r"(r2), "=r"(r3) : "r"(addr));
                bfr[nb * 2][0] = r0; bfr[nb * 2][1] = r1;
                bfr[nb * 2 + 1][0] = r2; bfr[nb * 2 + 1][1] = r3;
            }
#pragma unroll
            for (int mi = 0; mi < 4; ++mi)
#pragma unroll
                for (int ni = 0; ni < 8; ++ni)
                    asm volatile("mma.sync.aligned.m16n8k16.row.col.f16.f16.f16.f16 "
                        "{%0,%1},{%2,%3,%4,%5},{%6,%7},{%0,%1};\n"
                        : "+r"(acc[mi][ni][0]), "+r"(acc[mi][ni][1])
                        : "r"(a[mi][0]), "r"(a[mi][1]), "r"(a[mi][2]), "r"(a[mi][3]),
                          "r"(bfr[ni][0]), "r"(bfr[ni][1]));
        }
    }

    __half* Cb = g_covh + (size_t)b * W_ * W_;
    int g = lane >> 2, tg = lane & 3;
#pragma unroll
    for (int mi = 0; mi < 4; ++mi) {
        int m = bi * 128 + wm * 64 + mi * 16 + g;
#pragma unroll
        for (int ni = 0; ni < 8; ++ni) {
            int n2 = bj * 128 + wn * 64 + ni * 8 + tg * 2;
            *(uint32_t*)(Cb + (size_t)m * W_ + n2)       = acc[mi][ni][0];
            *(uint32_t*)(Cb + (size_t)(m + 8) * W_ + n2) = acc[mi][ni][1];
        }
    }
}

// ---------------- 3) merged: mu from psum + f~ / m~ from cov diagonal ----------------
__global__ __launch_bounds__(256) void muf_kernel() {
    int i = blockIdx.x * 256 + threadIdx.x;    // 32768 (b,w)
    int b = i >> 10, w = i & 1023;
    float s = 0.f;
#pragma unroll 8
    for (int c = 0; c < 64; ++c) s += g_psum[(size_t)(b * 64 + c) * W_ + w];
    float mu = s * (1.0f / T_);
    float diag = __half2float(g_covh[(size_t)b * W_ * W_ + (size_t)w * W_ + w]);
    float var = (diag - (float)T_ * mu * mu) * INV_TM1;
    float f = (var > 0.f) ? rsqrtf(var) : 0.f;
    g_ft[i] = f * sqrtf(INV_TM1);                         // f~
    g_mt[i] = mu * f * sqrtf((float)T_ * INV_TM1);        // m~
}

// ---------------- 4) EMA scan: 8 elems/thread, 16B cov loads (latency /4) ----------------
// corr = c * f~w * f~v  -  m~w * m~v    (algebraically == (c - T mw mv)/(T-1) * fw * fv)
__global__ __launch_bounds__(128) void ema_kernel(const float* __restrict__ ema_in,
                                                  float* __restrict__ ema_out) {
    int w = blockIdx.x;
    int tid = threadIdx.x;                      // 0..127
    int v0 = tid * 8;
    if (v0 + 7 < w) return;                     // whole chunk strictly below diagonal
    const uint4* cp = (const uint4*)(g_covh + (size_t)w * W_ + v0);

    float e[8];
#pragma unroll
    for (int j = 0; j < 8; ++j) e[j] = ema_in[(size_t)w * W_ + v0 + j];

#pragma unroll 4
    for (int b = 0; b < B_; ++b) {
        uint4 craw = __ldg(cp + (size_t)b * (W_ * W_ / 8));   // 4 half2 = 8 cov values
        float fwb = g_ft[b * W_ + w];
        float mwb = g_mt[b * W_ + w];
        float4 fv0 = *(const float4*)(g_ft + b * W_ + v0);
        float4 fv1 = *(const float4*)(g_ft + b * W_ + v0 + 4);
        float4 mv0 = *(const float4*)(g_mt + b * W_ + v0);
        float4 mv1 = *(const float4*)(g_mt + b * W_ + v0 + 4);
        float c[8];
        {
            float2 p;
            p = __half22float2(*(__half2*)&craw.x); c[0] = p.x; c[1] = p.y;
            p = __half22float2(*(__half2*)&craw.y); c[2] = p.x; c[3] = p.y;
            p = __half22float2(*(__half2*)&craw.z); c[4] = p.x; c[5] = p.y;
            p = __half22float2(*(__half2*)&craw.w); c[6] = p.x; c[7] = p.y;
        }
        float fv[8] = {fv0.x, fv0.y, fv0.z, fv0.w, fv1.x, fv1.y, fv1.z, fv1.w};
        float mv[8] = {mv0.x, mv0.y, mv0.z, mv0.w, mv1.x, mv1.y, mv1.z, mv1.w};
#pragma unroll
        for (int j = 0; j < 8; ++j) {
            float corr = fmaf(c[j], fwb * fv[j], -(mwb * mv[j]));
            corr = fminf(1.f, fmaxf(-1.f, corr));
            if (fabsf(corr) > 0.5f) e[j] = 0.9f * e[j] + 0.1f * corr;
        }
    }

    if (v0 >= w) {                               // fully upper chunk: vector stores
        *(float4*)(ema_out + (size_t)w * W_ + v0)     = make_float4(e[0], e[1], e[2], e[3]);
        *(float4*)(ema_out + (size_t)w * W_ + v0 + 4) = make_float4(e[4], e[5], e[6], e[7]);
    } else {                                     // straddles diagonal: element-wise
#pragma unroll
        for (int j = 0; j < 8; ++j)
            if (v0 + j >= w) ema_out[(size_t)w * W_ + v0 + j] = e[j];
    }
}

// ---------------- 4b) mirror: fill lower triangle via tiled smem transpose ----------------
__global__ __launch_bounds__(256) void mirror_kernel(float* __restrict__ ema_out) {
    int bid = blockIdx.x;                       // 0..527 upper (ti<=tj) 32x32 tiles
    int ti = 0, rem = bid, n = 32;
    while (rem >= n) { rem -= n; --n; ++ti; }
    int tj = ti + rem;

    __shared__ float tile[32][33];
    int tx = threadIdx.x & 31, ty = threadIdx.x >> 5;   // ty 0..7
#pragma unroll
    for (int k = 0; k < 4; ++k) {
        int r = k * 8 + ty;
        tile[r][tx] = ema_out[(size_t)(ti * 32 + r) * W_ + tj * 32 + tx];
    }
    __syncthreads();
    if (ti == tj) {
#pragma unroll
        for (int k = 0; k < 4; ++k) {
            int r = k * 8 + ty;
            if (tx < r) ema_out[(size_t)(ti * 32 + r) * W_ + ti * 32 + tx] = tile[tx][r];
        }
    } else {
#pragma unroll
        for (int k = 0; k < 4; ++k) {
            int r = k * 8 + ty;
            ema_out[(size_t)(tj * 32 + r) * W_ + ti * 32 + tx] = tile[tx][r];
        }
    }
}

// ---------------- 5) per-(g,b) off-diagonal |corr| partial sums (m~/f~ form) ----------------
__global__ __launch_bounds__(256) void corr_partial_kernel() {
    int g = blockIdx.x, b = blockIdx.y;
    const __half* covb = g_covh + (size_t)b * (W_ * W_);
    const float* fs   = g_ft + b * W_;
    const float* mn   = g_mt + b * W_;
    int tid = threadIdx.x;
    float s = 0.f;
    for (int i = tid; i < D_ * D_ / 2; i += 256) {      // 2048 half2 elements
        int d = i >> 5, j = i & 31;                      // row d, half2-col j
        int w = g * 64 + d, v = g * 64 + j * 2;
        float2 c2 = __half22float2(*(const __half2*)(covb + (size_t)w * W_ + v));
        float corr0 = fmaf(c2.x, fs[w] * fs[v],     -(mn[w] * mn[v]));
        float corr1 = fmaf(c2.y, fs[w] * fs[v + 1], -(mn[w] * mn[v + 1]));
        corr0 = fminf(1.f, fmaxf(-1.f, corr0));
        corr1 = fminf(1.f, fmaxf(-1.f, corr1));
        if (d != j * 2)     s += fabsf(corr0);
        if (d != j * 2 + 1) s += fabsf(corr1);
    }
    __shared__ float red[256];
    red[tid] = s;
    __syncthreads();
    for (int off = 128; off > 0; off >>= 1) {
        if (tid < off) red[tid] += red[tid + off];
        __syncthreads();
    }
    if (tid == 0) g_partial[b * G_ + g] = red[0];
}

__global__ void corr_final_kernel(float* __restrict__ out_corr) {
    int g = threadIdx.x;
    if (g < G_) {
        float s = 0.f;
        for (int b = 0; b < B_; ++b) s += g_partial[b * G_ + g];  // fixed order: deterministic
        out_corr[g] = s * (1.0f / ((float)(D_ * D_ - D_) * (float)B_));
    }
}

// ---------------- launch ----------------
extern "C" void kernel_launch(void* const* d_in, const int* in_sizes, int n_in,
                              void* d_out, int out_size) {
    (void)in_sizes; (void)n_in; (void)out_size;
    const float* x   = (const float*)d_in[0];
    const float* ema = (const float*)d_in[1];
    const float* W1  = (const float*)d_in[2];
    const float* b1  = (const float*)d_in[3];
    const float* W2  = (const float*)d_in[4];
    const float* b2  = (const float*)d_in[5];

    float* out      = (float*)d_out;                      // (B,T,G) = 1048576
    float* out_corr = out + (size_t)B_ * T_ * G_;         // (G,)    = 16
    float* out_ema  = out_corr + G_;                      // (W,W)   = 1048576

    fused_kernel<<<dim3(B_ * T_ / 32, 4), 256>>>(x, W1, b1, W2, b2, out);   // idx 0
    cov_mma_kernel<<<dim3(36, B_), 128>>>();                                // idx 1
    muf_kernel<<<(B_ * W_) / 256, 256>>>();                                 // idx 2
    ema_kernel<<<W_, 128>>>(ema, out_ema);                                  // idx 3
    mirror_kernel<<<528, 256>>>(out_ema);                                   // idx 4
    corr_partial_kernel<<<dim3(G_, B_), 256>>>();                           // idx 5
    corr_final_kernel<<<1, 32>>>(out_corr);                                 // idx 6
}